// round 6
// baseline (speedup 1.0000x reference)
#include <cuda_runtime.h>
#include <cuda_bf16.h>
#include <math.h>

constexpr int B_ = 2, T_ = 2048, E_ = 1024, H_ = 16, FFDIM = 4096, L_ = 4;
constexpr int M_ = B_ * T_;
constexpr int QKVW = 3 * E_;

// stage: Ah(10240) Al(10240) Bh(10240) Bl(10240) = 40960 B; 2 stages
constexpr int STAGE_B = 40960;
constexpr int SMEM_G = 2 * STAGE_B;

// ------------------------- device scratch (no allocs) -----------------------
__device__ float g_qkv[(size_t)M_ * QKVW];
__device__ float g_x[(size_t)M_ * E_];
__device__ float g_attn[(size_t)M_ * E_];
__device__ __nv_bfloat16 g_x_hi[(size_t)M_ * E_],  g_x_lo[(size_t)M_ * E_];
__device__ __nv_bfloat16 g_a_hi[(size_t)M_ * E_],  g_a_lo[(size_t)M_ * E_];
__device__ __nv_bfloat16 g_h_hi[(size_t)M_ * FFDIM], g_h_lo[(size_t)M_ * FFDIM];
__device__ __nv_bfloat16 g_wq_hi[(size_t)L_ * QKVW * E_], g_wq_lo[(size_t)L_ * QKVW * E_];
__device__ __nv_bfloat16 g_wp_hi[(size_t)L_ * E_ * E_],   g_wp_lo[(size_t)L_ * E_ * E_];
__device__ __nv_bfloat16 g_w1_hi[(size_t)L_ * FFDIM * E_], g_w1_lo[(size_t)L_ * FFDIM * E_];
__device__ __nv_bfloat16 g_w2_hi[(size_t)L_ * E_ * FFDIM], g_w2_lo[(size_t)L_ * E_ * FFDIM];

// ------------------------------- helpers ------------------------------------
__device__ __forceinline__ float gelu_tanh(float x) {
    float x3 = x * x * x;
    return 0.5f * x * (1.0f + tanhf(0.7978845608028654f * (x + 0.044715f * x3)));
}
__device__ __forceinline__ unsigned pack2(float lo, float hi) {
    unsigned r;
    asm("cvt.rn.bf16x2.f32 %0, %1, %2;" : "=r"(r) : "f"(hi), "f"(lo));
    return r;
}
__device__ __forceinline__ void split4(float4 v, unsigned& h0, unsigned& h1,
                                       unsigned& l0, unsigned& l1) {
    h0 = pack2(v.x, v.y); h1 = pack2(v.z, v.w);
    float rx = __uint_as_float(h0 << 16), ry = __uint_as_float(h0 & 0xFFFF0000u);
    float rz = __uint_as_float(h1 << 16), rw = __uint_as_float(h1 & 0xFFFF0000u);
    l0 = pack2(v.x - rx, v.y - ry); l1 = pack2(v.z - rz, v.w - rw);
}
__device__ __forceinline__ void ldmx4(unsigned* r, unsigned addr) {
    asm volatile("ldmatrix.sync.aligned.m8n8.x4.shared.b16 {%0,%1,%2,%3}, [%4];"
        : "=r"(r[0]), "=r"(r[1]), "=r"(r[2]), "=r"(r[3]) : "r"(addr));
}
__device__ __forceinline__ void ldmx4t(unsigned* r, unsigned addr) {
    asm volatile("ldmatrix.sync.aligned.m8n8.x4.trans.shared.b16 {%0,%1,%2,%3}, [%4];"
        : "=r"(r[0]), "=r"(r[1]), "=r"(r[2]), "=r"(r[3]) : "r"(addr));
}
__device__ __forceinline__ void mma16816(float* d, const unsigned* a, const unsigned* b) {
    asm volatile("mma.sync.aligned.m16n8k16.row.col.f32.bf16.bf16.f32 "
        "{%0,%1,%2,%3}, {%4,%5,%6,%7}, {%8,%9}, {%0,%1,%2,%3};"
        : "+f"(d[0]), "+f"(d[1]), "+f"(d[2]), "+f"(d[3])
        : "r"(a[0]), "r"(a[1]), "r"(a[2]), "r"(a[3]), "r"(b[0]), "r"(b[1]));
}
__device__ __forceinline__ void cpa16(unsigned dst, const void* src) {
    asm volatile("cp.async.cg.shared.global [%0], [%1], 16;" :: "r"(dst), "l"(src) : "memory");
}
__device__ __forceinline__ void cpa_commit() {
    asm volatile("cp.async.commit_group;" ::: "memory");
}
template <int W> __device__ __forceinline__ void cpa_wait() {
    asm volatile("cp.async.wait_group %0;" :: "n"(W) : "memory");
}

// --------------------- weight transpose + split pre-pass --------------------
// W fp32 [K][N]  ->  Th/Tl bf16 [N][K]
__global__ void __launch_bounds__(256) wt_kernel(
    const float* __restrict__ W, __nv_bfloat16* __restrict__ Th,
    __nv_bfloat16* __restrict__ Tl, int K, int N)
{
    __shared__ float sm[64][33];
    const int k0 = blockIdx.y * 64, n0 = blockIdx.x * 32, tid = threadIdx.x;
#pragma unroll
    for (int i = 0; i < 8; i++) {
        int f = tid + 256 * i, k = f >> 5, n = f & 31;
        sm[k][n] = W[(size_t)(k0 + k) * N + n0 + n];
    }
    __syncthreads();
#pragma unroll
    for (int i = 0; i < 4; i++) {
        int f = tid + 256 * i, n = f >> 5, kp = f & 31;
        float v0 = sm[2 * kp][n], v1 = sm[2 * kp + 1][n];
        unsigned hi = pack2(v0, v1);
        float r0 = __uint_as_float(hi << 16), r1 = __uint_as_float(hi & 0xFFFF0000u);
        unsigned lo = pack2(v0 - r0, v1 - r1);
        size_t o = (size_t)(n0 + n) * K + k0 + 2 * kp;
        *reinterpret_cast<unsigned*>(&Th[o]) = hi;
        *reinterpret_cast<unsigned*>(&Tl[o]) = lo;
    }
}

// ------------------------- fp32 -> hi/lo plane split ------------------------
__global__ void split_kernel(const float4* __restrict__ in,
                             uint2* __restrict__ oh, uint2* __restrict__ ol, int n4)
{
    int i = blockIdx.x * blockDim.x + threadIdx.x;
    if (i >= n4) return;
    unsigned h0, h1, l0, l1;
    split4(in[i], h0, h1, l0, l1);
    oh[i] = make_uint2(h0, h1);
    ol[i] = make_uint2(l0, l1);
}

// ----------------------- plane-fed mma.sync GEMM ----------------------------
// C[M,N] = epi(A @ B^T + bias); A planes [M][K], B planes [N][K], bf16 K-major.
// 128x128 tile, BK=32, 256 thr (8 warps, 64x32 warp tiles), cp.async 2-stage.
template <int ACT, bool RES, bool WF32, bool WPL>
__global__ void __launch_bounds__(256) gemm_bf(
    const __nv_bfloat16* __restrict__ Ah, const __nv_bfloat16* __restrict__ Al,
    const __nv_bfloat16* __restrict__ Bh, const __nv_bfloat16* __restrict__ Bl,
    const float* __restrict__ bias, const float* __restrict__ res,
    float* __restrict__ C, __nv_bfloat16* __restrict__ Ch, __nv_bfloat16* __restrict__ Cl,
    int M, int N, int K)
{
    extern __shared__ char smem[];
    const unsigned sb = (unsigned)__cvta_generic_to_shared(smem);
    const int tid = threadIdx.x, lane = tid & 31, warp = tid >> 5;
    const int bm = blockIdx.y * 128, bn = blockIdx.x * 128;
    const int wm = (warp >> 2) * 64, wn = (warp & 3) * 32;

    float acc[4][4][4];
#pragma unroll
    for (int i = 0; i < 4; i++)
#pragma unroll
        for (int j = 0; j < 4; j++)
#pragma unroll
            for (int t = 0; t < 4; t++) acc[i][j][t] = 0.0f;

    const int S = K >> 5;
    auto stage = [&](int s) {
        unsigned base = sb + (s & 1) * STAGE_B;
        int k0 = s << 5;
#pragma unroll
        for (int i = 0; i < 2; i++) {
            int f = tid + 256 * i;          // 512 chunks of 16B per plane
            int r = f >> 2, c = f & 3;
            unsigned so = base + (unsigned)(r * 80 + c * 16);
            size_t ga = (size_t)(bm + r) * K + k0 + c * 8;
            size_t gb = (size_t)(bn + r) * K + k0 + c * 8;
            cpa16(so,          Ah + ga);
            cpa16(so + 10240,  Al + ga);
            cpa16(so + 20480,  Bh + gb);
            cpa16(so + 30720,  Bl + gb);
        }
        cpa_commit();
    };

    stage(0);
    stage(1);

    for (int s = 0; s < S; s++) {
        cpa_wait<1>();
        __syncthreads();
        unsigned base = sb + (s & 1) * STAGE_B;

#pragma unroll
        for (int ks = 0; ks < 32; ks += 16) {
            // B fragments: rows = n (K-major), non-trans ldmatrix
            unsigned bhreg[2][4], blreg[2][4];
#pragma unroll
            for (int g = 0; g < 2; g++) {
                unsigned boff = base + 20480 +
                    (unsigned)((wn + g * 16 + (lane & 15)) * 80 + (ks + ((lane >> 4) << 3)) * 2);
                ldmx4(bhreg[g], boff);
                ldmx4(blreg[g], boff + 10240);
            }
#pragma unroll
            for (int ma = 0; ma < 4; ma++) {
                unsigned aoff = base +
                    (unsigned)((wm + ma * 16 + (lane & 15)) * 80 + (ks + ((lane >> 4) << 3)) * 2);
                unsigned ah[4], al[4];
                ldmx4(ah, aoff);
                ldmx4(al, aoff + 10240);
#pragma unroll
                for (int na = 0; na < 4; na++) {
                    int g = na >> 1, o = na & 1;
                    unsigned bhp[2] = { bhreg[g][o], bhreg[g][o + 2] };
                    unsigned blp[2] = { blreg[g][o], blreg[g][o + 2] };
                    mma16816(acc[ma][na], ah, bhp);
                    mma16816(acc[ma][na], ah, blp);
                    mma16816(acc[ma][na], al, bhp);
                }
            }
        }

        __syncthreads();
        if (s + 2 < S) stage(s + 2);
    }

    // ---------------- epilogue (fragment layout) ----------------
#pragma unroll
    for (int ma = 0; ma < 4; ma++) {
        int r0 = bm + wm + ma * 16 + (lane >> 2);
#pragma unroll
        for (int na = 0; na < 4; na++) {
            int c0 = bn + wn + na * 8 + ((lane & 3) << 1);
            float b0v = bias[c0], b1v = bias[c0 + 1];
            float v00 = acc[ma][na][0] + b0v, v01 = acc[ma][na][1] + b1v;
            float v10 = acc[ma][na][2] + b0v, v11 = acc[ma][na][3] + b1v;
            if (ACT == 1) {
                v00 = gelu_tanh(v00); v01 = gelu_tanh(v01);
                v10 = gelu_tanh(v10); v11 = gelu_tanh(v11);
            }
            if (RES) {
                v00 += res[(size_t)r0 * N + c0];
                v01 += res[(size_t)r0 * N + c0 + 1];
                v10 += res[(size_t)(r0 + 8) * N + c0];
                v11 += res[(size_t)(r0 + 8) * N + c0 + 1];
            }
            if (WF32) {
                *reinterpret_cast<float2*>(&C[(size_t)r0 * N + c0]) = make_float2(v00, v01);
                *reinterpret_cast<float2*>(&C[(size_t)(r0 + 8) * N + c0]) = make_float2(v10, v11);
            }
            if (WPL) {
                unsigned h0 = pack2(v00, v01);
                float rx = __uint_as_float(h0 << 16), ry = __uint_as_float(h0 & 0xFFFF0000u);
                unsigned l0 = pack2(v00 - rx, v01 - ry);
                unsigned h1 = pack2(v10, v11);
                float rz = __uint_as_float(h1 << 16), rw = __uint_as_float(h1 & 0xFFFF0000u);
                unsigned l1 = pack2(v10 - rz, v11 - rw);
                *reinterpret_cast<unsigned*>(&Ch[(size_t)r0 * N + c0]) = h0;
                *reinterpret_cast<unsigned*>(&Cl[(size_t)r0 * N + c0]) = l0;
                *reinterpret_cast<unsigned*>(&Ch[(size_t)(r0 + 8) * N + c0]) = h1;
                *reinterpret_cast<unsigned*>(&Cl[(size_t)(r0 + 8) * N + c0]) = l1;
            }
        }
    }
}

// ------------------- flash attention (verified round-3 version) -------------
__global__ void __launch_bounds__(256) attn_mma(
    const float* __restrict__ qkv, float* __restrict__ out)
{
    __shared__ __align__(16) unsigned short sm[18432];

    const int b = blockIdx.y >> 4;
    const int h = blockIdx.y & 15;
    const int q0 = blockIdx.x * 128;
    const int tid = threadIdx.x;
    const int lane = tid & 31;
    const int warp = tid >> 5;
    const float* base = qkv + (size_t)b * T_ * QKVW;
    const int hc = h * 64;

    unsigned short* Qh = sm;
    unsigned short* Ql = sm + 9216;
#pragma unroll
    for (int i = 0; i < 8; i++) {
        int f = tid + 256 * i;
        int r = f >> 4;
        int c = (f & 15) << 2;
        float4 v = *reinterpret_cast<const float4*>(
            &base[(size_t)(q0 + r) * QKVW + hc + c]);
        v.x *= 0.125f; v.y *= 0.125f; v.z *= 0.125f; v.w *= 0.125f;
        unsigned h0, h1, l0, l1;
        split4(v, h0, h1, l0, l1);
        *reinterpret_cast<uint2*>(&Qh[r * 72 + c]) = make_uint2(h0, h1);
        *reinterpret_cast<uint2*>(&Ql[r * 72 + c]) = make_uint2(l0, l1);
    }
    __syncthreads();

    unsigned qh[4][4], ql[4][4];
#pragma unroll
    for (int ks = 0; ks < 4; ks++) {
        int row = warp * 16 + (lane & 15);
        int col = ks * 16 + ((lane >> 4) << 3);
        ldmx4(qh[ks], (unsigned)__cvta_generic_to_shared(&Qh[row * 72 + col]));
        ldmx4(ql[ks], (unsigned)__cvta_generic_to_shared(&Ql[row * 72 + col]));
    }
    __syncthreads();

    unsigned short* Kh = sm;
    unsigned short* Kl = sm + 4608;
    unsigned short* Vh = sm + 9216;
    unsigned short* Vl = sm + 13824;

    float oacc[8][4];
#pragma unroll
    for (int t = 0; t < 8; t++)
#pragma unroll
        for (int j = 0; j < 4; j++) oacc[t][j] = 0.0f;
    float m0 = -1e30f, m1 = -1e30f, lsum0 = 0.0f, lsum1 = 0.0f;

    float4 Kr[4], Vr[4];
    auto load_kv = [&](int kt) {
#pragma unroll
        for (int i = 0; i < 4; i++) {
            int f = tid + 256 * i;
            int r = f >> 4, c = (f & 15) << 2;
            Kr[i] = *reinterpret_cast<const float4*>(
                &base[(size_t)(kt + r) * QKVW + E_ + hc + c]);
            Vr[i] = *reinterpret_cast<const float4*>(
                &base[(size_t)(kt + r) * QKVW + 2 * E_ + hc + c]);
        }
    };
    auto stage_kv = [&]() {
#pragma unroll
        for (int i = 0; i < 4; i++) {
            int f = tid + 256 * i;
            int r = f >> 4, c = (f & 15) << 2;
            unsigned h0, h1, l0, l1;
            split4(Kr[i], h0, h1, l0, l1);
            *reinterpret_cast<uint2*>(&Kh[r * 72 + c]) = make_uint2(h0, h1);
            *reinterpret_cast<uint2*>(&Kl[r * 72 + c]) = make_uint2(l0, l1);
            split4(Vr[i], h0, h1, l0, l1);
            *reinterpret_cast<uint2*>(&Vh[r * 72 + c]) = make_uint2(h0, h1);
            *reinterpret_cast<uint2*>(&Vl[r * 72 + c]) = make_uint2(l0, l1);
        }
    };

    load_kv(0);
    stage_kv();
    __syncthreads();

    constexpr int NIT = T_ / 64;
    for (int it = 0; it < NIT; it++) {
        if (it + 1 < NIT) load_kv((it + 1) * 64);

        float sacc[8][4];
#pragma unroll
        for (int t = 0; t < 8; t++)
#pragma unroll
            for (int j = 0; j < 4; j++) sacc[t][j] = 0.0f;

#pragma unroll
        for (int ks = 0; ks < 4; ks++) {
#pragma unroll
            for (int g = 0; g < 4; g++) {
                int row = g * 16 + ((lane >> 4) << 3) + (lane & 7);
                int col = ks * 16 + (((lane >> 3) & 1) << 3);
                unsigned bh[4], bl[4];
                ldmx4(bh, (unsigned)__cvta_generic_to_shared(&Kh[row * 72 + col]));
                ldmx4(bl, (unsigned)__cvta_generic_to_shared(&Kl[row * 72 + col]));
                mma16816(sacc[2 * g],     qh[ks], &bh[0]);
                mma16816(sacc[2 * g],     qh[ks], &bl[0]);
                mma16816(sacc[2 * g],     ql[ks], &bh[0]);
                mma16816(sacc[2 * g + 1], qh[ks], &bh[2]);
                mma16816(sacc[2 * g + 1], qh[ks], &bl[2]);
                mma16816(sacc[2 * g + 1], ql[ks], &bh[2]);
            }
        }

        float mx0 = -1e30f, mx1 = -1e30f;
#pragma unroll
        for (int t = 0; t < 8; t++) {
            mx0 = fmaxf(mx0, fmaxf(sacc[t][0], sacc[t][1]));
            mx1 = fmaxf(mx1, fmaxf(sacc[t][2], sacc[t][3]));
        }
        mx0 = fmaxf(mx0, __shfl_xor_sync(0xffffffffu, mx0, 1));
        mx0 = fmaxf(mx0, __shfl_xor_sync(0xffffffffu, mx0, 2));
        mx1 = fmaxf(mx1, __shfl_xor_sync(0xffffffffu, mx1, 1));
        mx1 = fmaxf(mx1, __shfl_xor_sync(0xffffffffu, mx1, 2));
        float mn0 = fmaxf(m0, mx0), mn1 = fmaxf(m1, mx1);
        float c0 = __expf(m0 - mn0), c1 = __expf(m1 - mn1);
        m0 = mn0; m1 = mn1;
        float s0 = 0.0f, s1 = 0.0f;
#pragma unroll
        for (int t = 0; t < 8; t++) {
            sacc[t][0] = __expf(sacc[t][0] - m0);
            sacc[t][1] = __expf(sacc[t][1] - m0);
            sacc[t][2] = __expf(sacc[t][2] - m1);
            sacc[t][3] = __expf(sacc[t][3] - m1);
            s0 += sacc[t][0] + sacc[t][1];
            s1 += sacc[t][2] + sacc[t][3];
        }
        s0 += __shfl_xor_sync(0xffffffffu, s0, 1);
        s0 += __shfl_xor_sync(0xffffffffu, s0, 2);
        s1 += __shfl_xor_sync(0xffffffffu, s1, 1);
        s1 += __shfl_xor_sync(0xffffffffu, s1, 2);
        lsum0 = lsum0 * c0 + s0;
        lsum1 = lsum1 * c1 + s1;
#pragma unroll
        for (int t = 0; t < 8; t++) {
            oacc[t][0] *= c0; oacc[t][1] *= c0;
            oacc[t][2] *= c1; oacc[t][3] *= c1;
        }

#pragma unroll
        for (int kk = 0; kk < 4; kk++) {
            unsigned ph[4], pl[4];
            ph[0] = pack2(sacc[2 * kk][0], sacc[2 * kk][1]);
            ph[1] = pack2(sacc[2 * kk][2], sacc[2 * kk][3]);
            ph[2] = pack2(sacc[2 * kk + 1][0], sacc[2 * kk + 1][1]);
            ph[3] = pack2(sacc[2 * kk + 1][2], sacc[2 * kk + 1][3]);
#pragma unroll
            for (int u2 = 0; u2 < 4; u2++) {
                const float* p = sacc[2 * kk + (u2 >> 1)];
                int o = (u2 & 1) * 2;
                float rx = __uint_as_float(ph[u2] << 16);
                float ry = __uint_as_float(ph[u2] & 0xFFFF0000u);
                pl[u2] = pack2(p[o] - rx, p[o + 1] - ry);
            }
#pragma unroll
            for (int g = 0; g < 4; g++) {
                int row = kk * 16 + (((lane >> 3) & 1) << 3) + (lane & 7);
                int col = g * 16 + ((lane >> 4) << 3);
                unsigned vh[4], vl[4];
                ldmx4t(vh, (unsigned)__cvta_generic_to_shared(&Vh[row * 72 + col]));
                ldmx4t(vl, (unsigned)__cvta_generic_to_shared(&Vl[row * 72 + col]));
                mma16816(oacc[2 * g],     ph, &vh[0]);
                mma16816(oacc[2 * g],     ph, &vl[0]);
                mma16816(oacc[2 * g],     pl, &vh[0]);
                mma16816(oacc[2 * g + 1], ph, &vh[2]);
                mma16816(oacc[2 * g + 1], ph, &vl[2]);
                mma16816(oacc[2 * g + 1], pl, &vh[2]);
            }
        }

        if (it + 1 < NIT) {
            __syncthreads();
            stage_kv();
            __syncthreads();
        }
    }

    float inv0 = 1.0f / lsum0, inv1 = 1.0f / lsum1;
    int r0 = q0 + warp * 16 + (lane >> 2);
#pragma unroll
    for (int t = 0; t < 8; t++) {
        int col = hc + t * 8 + ((lane & 3) << 1);
        *reinterpret_cast<float2*>(&out[((size_t)b * T_ + r0) * E_ + col]) =
            make_float2(oacc[t][0] * inv0, oacc[t][1] * inv0);
        *reinterpret_cast<float2*>(&out[((size_t)b * T_ + r0 + 8) * E_ + col]) =
            make_float2(oacc[t][2] * inv1, oacc[t][3] * inv1);
    }
}

// ------------------------------ orchestration -------------------------------
extern "C" void kernel_launch(void* const* d_in, const int* in_sizes, int n_in,
                              void* d_out, int out_size)
{
    const float* x_in  = (const float*)d_in[0];
    const float* Wqkv  = (const float*)d_in[1];
    const float* bqkv  = (const float*)d_in[2];
    const float* Wproj = (const float*)d_in[3];
    const float* bproj = (const float*)d_in[4];
    const float* W1    = (const float*)d_in[5];
    const float* b1    = (const float*)d_in[6];
    const float* W2    = (const float*)d_in[7];
    const float* b2    = (const float*)d_in[8];
    float* out = (float*)d_out;

    cudaFuncSetAttribute(gemm_bf<0, false, true, false>,
                         cudaFuncAttributeMaxDynamicSharedMemorySize, SMEM_G);
    cudaFuncSetAttribute(gemm_bf<0, true, true, true>,
                         cudaFuncAttributeMaxDynamicSharedMemorySize, SMEM_G);
    cudaFuncSetAttribute(gemm_bf<1, false, false, true>,
                         cudaFuncAttributeMaxDynamicSharedMemorySize, SMEM_G);

    float *gqkv, *gx, *gattn;
    __nv_bfloat16 *gxh, *gxl, *gah, *gal, *ghh, *ghl;
    __nv_bfloat16 *wqh, *wql, *wph, *wpl_, *w1h, *w1l, *w2h, *w2l;
    cudaGetSymbolAddress((void**)&gqkv, g_qkv);
    cudaGetSymbolAddress((void**)&gx, g_x);
    cudaGetSymbolAddress((void**)&gattn, g_attn);
    cudaGetSymbolAddress((void**)&gxh, g_x_hi);  cudaGetSymbolAddress((void**)&gxl, g_x_lo);
    cudaGetSymbolAddress((void**)&gah, g_a_hi);  cudaGetSymbolAddress((void**)&gal, g_a_lo);
    cudaGetSymbolAddress((void**)&ghh, g_h_hi);  cudaGetSymbolAddress((void**)&ghl, g_h_lo);
    cudaGetSymbolAddress((void**)&wqh, g_wq_hi); cudaGetSymbolAddress((void**)&wql, g_wq_lo);
    cudaGetSymbolAddress((void**)&wph, g_wp_hi); cudaGetSymbolAddress((void**)&wpl_, g_wp_lo);
    cudaGetSymbolAddress((void**)&w1h, g_w1_hi); cudaGetSymbolAddress((void**)&w1l, g_w1_lo);
    cudaGetSymbolAddress((void**)&w2h, g_w2_hi); cudaGetSymbolAddress((void**)&w2l, g_w2_lo);

    // weight transpose+split pre-pass ([K][N] fp32 -> [N][K] bf16 hi/lo)
    for (int l = 0; l < L_; l++) {
        wt_kernel<<<dim3(QKVW / 32, E_ / 64), 256>>>(
            Wqkv + (size_t)l * E_ * QKVW, wqh + (size_t)l * QKVW * E_,
            wql + (size_t)l * QKVW * E_, E_, QKVW);
        wt_kernel<<<dim3(E_ / 32, E_ / 64), 256>>>(
            Wproj + (size_t)l * E_ * E_, wph + (size_t)l * E_ * E_,
            wpl_ + (size_t)l * E_ * E_, E_, E_);
        wt_kernel<<<dim3(FFDIM / 32, E_ / 64), 256>>>(
            W1 + (size_t)l * E_ * FFDIM, w1h + (size_t)l * (size_t)FFDIM * E_,
            w1l + (size_t)l * (size_t)FFDIM * E_, E_, FFDIM);
        wt_kernel<<<dim3(E_ / 32, FFDIM / 64), 256>>>(
            W2 + (size_t)l * FFDIM * E_, w2h + (size_t)l * (size_t)E_ * FFDIM,
            w2l + (size_t)l * (size_t)E_ * FFDIM, FFDIM, E_);
    }
    // x0 planes
    split_kernel<<<(M_ * E_ / 4) / 256, 256>>>(
        (const float4*)x_in, (uint2*)gxh, (uint2*)gxl, M_ * E_ / 4);

    for (int l = 0; l < L_; l++) {
        const float* xcur = (l == 0) ? x_in : gx;

        // QKV: fp32 out for attention
        gemm_bf<0, false, true, false><<<dim3(QKVW / 128, M_ / 128), 256, SMEM_G>>>(
            gxh, gxl, wqh + (size_t)l * QKVW * E_, wql + (size_t)l * QKVW * E_,
            bqkv + (size_t)l * QKVW, nullptr, gqkv, nullptr, nullptr, M_, QKVW, E_);

        attn_mma<<<dim3(T_ / 128, B_ * H_), 256>>>(gqkv, gattn);
        split_kernel<<<(M_ * E_ / 4) / 256, 256>>>(
            (const float4*)gattn, (uint2*)gah, (uint2*)gal, M_ * E_ / 4);

        // proj + residual: fp32 x + planes
        gemm_bf<0, true, true, true><<<dim3(E_ / 128, M_ / 128), 256, SMEM_G>>>(
            gah, gal, wph + (size_t)l * E_ * E_, wpl_ + (size_t)l * E_ * E_,
            bproj + (size_t)l * E_, xcur, gx, gxh, gxl, M_, E_, E_);

        // MLP up + GELU: planes only
        gemm_bf<1, false, false, true><<<dim3(FFDIM / 128, M_ / 128), 256, SMEM_G>>>(
            gxh, gxl, w1h + (size_t)l * (size_t)FFDIM * E_,
            w1l + (size_t)l * (size_t)FFDIM * E_,
            b1 + (size_t)l * FFDIM, nullptr, nullptr, ghh, ghl, M_, FFDIM, E_);

        // MLP down + residual: fp32 (out / gx) + planes for next layer
        float* dst = (l == L_ - 1) ? out : gx;
        gemm_bf<0, true, true, true><<<dim3(E_ / 128, M_ / 128), 256, SMEM_G>>>(
            ghh, ghl, w2h + (size_t)l * (size_t)E_ * FFDIM,
            w2l + (size_t)l * (size_t)E_ * FFDIM,
            b2 + (size_t)l * E_, gx, dst, gxh, gxl, M_, E_, FFDIM);
    }
}

// round 7
// speedup vs baseline: 1.0125x; 1.0125x over previous
#include <cuda_runtime.h>
#include <cuda_bf16.h>
#include <math.h>

constexpr int B_ = 2, T_ = 2048, E_ = 1024, H_ = 16, FFDIM = 4096, L_ = 4;
constexpr int M_ = B_ * T_;
constexpr int QKVW = 3 * E_;

// stage: Ah(10240) Al(10240) Bh(10240) Bl(10240) = 40960 B; 2 stages
constexpr int STAGE_B = 40960;
constexpr int SMEM_G = 2 * STAGE_B;

// ------------------------- device scratch (no allocs) -----------------------
__device__ float g_qkv[(size_t)M_ * QKVW];
__device__ float g_x[(size_t)M_ * E_];
__device__ float g_attn[(size_t)M_ * E_];
__device__ __nv_bfloat16 g_x_hi[(size_t)M_ * E_],  g_x_lo[(size_t)M_ * E_];
__device__ __nv_bfloat16 g_a_hi[(size_t)M_ * E_],  g_a_lo[(size_t)M_ * E_];
__device__ __nv_bfloat16 g_h_hi[(size_t)M_ * FFDIM], g_h_lo[(size_t)M_ * FFDIM];
__device__ __nv_bfloat16 g_wq_hi[(size_t)L_ * QKVW * E_], g_wq_lo[(size_t)L_ * QKVW * E_];
__device__ __nv_bfloat16 g_wp_hi[(size_t)L_ * E_ * E_],   g_wp_lo[(size_t)L_ * E_ * E_];
__device__ __nv_bfloat16 g_w1_hi[(size_t)L_ * FFDIM * E_], g_w1_lo[(size_t)L_ * FFDIM * E_];
__device__ __nv_bfloat16 g_w2_hi[(size_t)L_ * E_ * FFDIM], g_w2_lo[(size_t)L_ * E_ * FFDIM];

// ------------------------------- helpers ------------------------------------
__device__ __forceinline__ float gelu_tanh(float x) {
    float x3 = x * x * x;
    return 0.5f * x * (1.0f + tanhf(0.7978845608028654f * (x + 0.044715f * x3)));
}
__device__ __forceinline__ unsigned pack2(float lo, float hi) {
    unsigned r;
    asm("cvt.rn.bf16x2.f32 %0, %1, %2;" : "=r"(r) : "f"(hi), "f"(lo));
    return r;
}
__device__ __forceinline__ void split4(float4 v, unsigned& h0, unsigned& h1,
                                       unsigned& l0, unsigned& l1) {
    h0 = pack2(v.x, v.y); h1 = pack2(v.z, v.w);
    float rx = __uint_as_float(h0 << 16), ry = __uint_as_float(h0 & 0xFFFF0000u);
    float rz = __uint_as_float(h1 << 16), rw = __uint_as_float(h1 & 0xFFFF0000u);
    l0 = pack2(v.x - rx, v.y - ry); l1 = pack2(v.z - rz, v.w - rw);
}
__device__ __forceinline__ void ldmx4(unsigned* r, unsigned addr) {
    asm volatile("ldmatrix.sync.aligned.m8n8.x4.shared.b16 {%0,%1,%2,%3}, [%4];"
        : "=r"(r[0]), "=r"(r[1]), "=r"(r[2]), "=r"(r[3]) : "r"(addr));
}
__device__ __forceinline__ void ldmx4t(unsigned* r, unsigned addr) {
    asm volatile("ldmatrix.sync.aligned.m8n8.x4.trans.shared.b16 {%0,%1,%2,%3}, [%4];"
        : "=r"(r[0]), "=r"(r[1]), "=r"(r[2]), "=r"(r[3]) : "r"(addr));
}
__device__ __forceinline__ void mma16816(float* d, const unsigned* a, const unsigned* b) {
    asm volatile("mma.sync.aligned.m16n8k16.row.col.f32.bf16.bf16.f32 "
        "{%0,%1,%2,%3}, {%4,%5,%6,%7}, {%8,%9}, {%0,%1,%2,%3};"
        : "+f"(d[0]), "+f"(d[1]), "+f"(d[2]), "+f"(d[3])
        : "r"(a[0]), "r"(a[1]), "r"(a[2]), "r"(a[3]), "r"(b[0]), "r"(b[1]));
}
__device__ __forceinline__ void cpa16(unsigned dst, const void* src) {
    asm volatile("cp.async.cg.shared.global [%0], [%1], 16;" :: "r"(dst), "l"(src) : "memory");
}
__device__ __forceinline__ void cpa_commit() {
    asm volatile("cp.async.commit_group;" ::: "memory");
}
template <int W> __device__ __forceinline__ void cpa_wait() {
    asm volatile("cp.async.wait_group %0;" :: "n"(W) : "memory");
}

// --------------------- weight transpose + split pre-pass --------------------
// W fp32 [K][N]  ->  Th/Tl bf16 [N][K]
__global__ void __launch_bounds__(256) wt_kernel(
    const float* __restrict__ W, __nv_bfloat16* __restrict__ Th,
    __nv_bfloat16* __restrict__ Tl, int K, int N)
{
    __shared__ float sm[64][33];
    const int k0 = blockIdx.y * 64, n0 = blockIdx.x * 32, tid = threadIdx.x;
#pragma unroll
    for (int i = 0; i < 8; i++) {
        int f = tid + 256 * i, k = f >> 5, n = f & 31;
        sm[k][n] = W[(size_t)(k0 + k) * N + n0 + n];
    }
    __syncthreads();
#pragma unroll
    for (int i = 0; i < 4; i++) {
        int f = tid + 256 * i, n = f >> 5, kp = f & 31;
        float v0 = sm[2 * kp][n], v1 = sm[2 * kp + 1][n];
        unsigned hi = pack2(v0, v1);
        float r0 = __uint_as_float(hi << 16), r1 = __uint_as_float(hi & 0xFFFF0000u);
        unsigned lo = pack2(v0 - r0, v1 - r1);
        size_t o = (size_t)(n0 + n) * K + k0 + 2 * kp;
        *reinterpret_cast<unsigned*>(&Th[o]) = hi;
        *reinterpret_cast<unsigned*>(&Tl[o]) = lo;
    }
}

// ------------------------- fp32 -> hi/lo plane split ------------------------
__global__ void split_kernel(const float4* __restrict__ in,
                             uint2* __restrict__ oh, uint2* __restrict__ ol, int n4)
{
    int i = blockIdx.x * blockDim.x + threadIdx.x;
    if (i >= n4) return;
    unsigned h0, h1, l0, l1;
    split4(in[i], h0, h1, l0, l1);
    oh[i] = make_uint2(h0, h1);
    ol[i] = make_uint2(l0, l1);
}

// ----------------------- plane-fed mma.sync GEMM ----------------------------
// C[M,N] = epi(A @ B^T + bias); A planes [M][K], B planes [N][K], bf16 K-major.
// 128x128 tile, BK=32, 256 thr (8 warps, 64x32 warp tiles), cp.async 2-stage.
// __launch_bounds__(256, 2): cap regs at 128 so 2 CTAs/SM fit the RF.
template <int ACT, bool RES, bool WF32, bool WPL>
__global__ void __launch_bounds__(256, 2) gemm_bf(
    const __nv_bfloat16* __restrict__ Ah, const __nv_bfloat16* __restrict__ Al,
    const __nv_bfloat16* __restrict__ Bh, const __nv_bfloat16* __restrict__ Bl,
    const float* __restrict__ bias, const float* __restrict__ res,
    float* __restrict__ C, __nv_bfloat16* __restrict__ Ch, __nv_bfloat16* __restrict__ Cl,
    int M, int N, int K)
{
    extern __shared__ char smem[];
    const unsigned sb = (unsigned)__cvta_generic_to_shared(smem);
    const int tid = threadIdx.x, lane = tid & 31, warp = tid >> 5;
    const int bm = blockIdx.y * 128, bn = blockIdx.x * 128;
    const int wm = (warp >> 2) * 64, wn = (warp & 3) * 32;

    float acc[4][4][4];
#pragma unroll
    for (int i = 0; i < 4; i++)
#pragma unroll
        for (int j = 0; j < 4; j++)
#pragma unroll
            for (int t = 0; t < 4; t++) acc[i][j][t] = 0.0f;

    const int S = K >> 5;
    auto stage = [&](int s) {
        unsigned base = sb + (s & 1) * STAGE_B;
        int k0 = s << 5;
#pragma unroll
        for (int i = 0; i < 2; i++) {
            int f = tid + 256 * i;          // 512 chunks of 16B per plane
            int r = f >> 2, c = f & 3;
            unsigned so = base + (unsigned)(r * 80 + c * 16);
            size_t ga = (size_t)(bm + r) * K + k0 + c * 8;
            size_t gb = (size_t)(bn + r) * K + k0 + c * 8;
            cpa16(so,          Ah + ga);
            cpa16(so + 10240,  Al + ga);
            cpa16(so + 20480,  Bh + gb);
            cpa16(so + 30720,  Bl + gb);
        }
        cpa_commit();
    };

    stage(0);
    stage(1);

    for (int s = 0; s < S; s++) {
        cpa_wait<1>();
        __syncthreads();
        unsigned base = sb + (s & 1) * STAGE_B;

#pragma unroll
        for (int ks = 0; ks < 32; ks += 16) {
            unsigned bhreg[2][4], blreg[2][4];
#pragma unroll
            for (int g = 0; g < 2; g++) {
                unsigned boff = base + 20480 +
                    (unsigned)((wn + g * 16 + (lane & 15)) * 80 + (ks + ((lane >> 4) << 3)) * 2);
                ldmx4(bhreg[g], boff);
                ldmx4(blreg[g], boff + 10240);
            }
#pragma unroll
            for (int ma = 0; ma < 4; ma++) {
                unsigned aoff = base +
                    (unsigned)((wm + ma * 16 + (lane & 15)) * 80 + (ks + ((lane >> 4) << 3)) * 2);
                unsigned ah[4], al[4];
                ldmx4(ah, aoff);
                ldmx4(al, aoff + 10240);
#pragma unroll
                for (int na = 0; na < 4; na++) {
                    int g = na >> 1, o = na & 1;
                    unsigned bhp[2] = { bhreg[g][o], bhreg[g][o + 2] };
                    unsigned blp[2] = { blreg[g][o], blreg[g][o + 2] };
                    mma16816(acc[ma][na], ah, bhp);
                    mma16816(acc[ma][na], ah, blp);
                    mma16816(acc[ma][na], al, bhp);
                }
            }
        }

        __syncthreads();
        if (s + 2 < S) stage(s + 2);
    }

    // ---------------- epilogue (fragment layout) ----------------
#pragma unroll
    for (int ma = 0; ma < 4; ma++) {
        int r0 = bm + wm + ma * 16 + (lane >> 2);
#pragma unroll
        for (int na = 0; na < 4; na++) {
            int c0 = bn + wn + na * 8 + ((lane & 3) << 1);
            float b0v = bias[c0], b1v = bias[c0 + 1];
            float v00 = acc[ma][na][0] + b0v, v01 = acc[ma][na][1] + b1v;
            float v10 = acc[ma][na][2] + b0v, v11 = acc[ma][na][3] + b1v;
            if (ACT == 1) {
                v00 = gelu_tanh(v00); v01 = gelu_tanh(v01);
                v10 = gelu_tanh(v10); v11 = gelu_tanh(v11);
            }
            if (RES) {
                v00 += res[(size_t)r0 * N + c0];
                v01 += res[(size_t)r0 * N + c0 + 1];
                v10 += res[(size_t)(r0 + 8) * N + c0];
                v11 += res[(size_t)(r0 + 8) * N + c0 + 1];
            }
            if (WF32) {
                *reinterpret_cast<float2*>(&C[(size_t)r0 * N + c0]) = make_float2(v00, v01);
                *reinterpret_cast<float2*>(&C[(size_t)(r0 + 8) * N + c0]) = make_float2(v10, v11);
            }
            if (WPL) {
                unsigned h0 = pack2(v00, v01);
                float rx = __uint_as_float(h0 << 16), ry = __uint_as_float(h0 & 0xFFFF0000u);
                unsigned l0 = pack2(v00 - rx, v01 - ry);
                unsigned h1 = pack2(v10, v11);
                float rz = __uint_as_float(h1 << 16), rw = __uint_as_float(h1 & 0xFFFF0000u);
                unsigned l1 = pack2(v10 - rz, v11 - rw);
                *reinterpret_cast<unsigned*>(&Ch[(size_t)r0 * N + c0]) = h0;
                *reinterpret_cast<unsigned*>(&Cl[(size_t)r0 * N + c0]) = l0;
                *reinterpret_cast<unsigned*>(&Ch[(size_t)(r0 + 8) * N + c0]) = h1;
                *reinterpret_cast<unsigned*>(&Cl[(size_t)(r0 + 8) * N + c0]) = l1;
            }
        }
    }
}

// ------------------- flash attention (verified round-3 version) -------------
__global__ void __launch_bounds__(256) attn_mma(
    const float* __restrict__ qkv, float* __restrict__ out)
{
    __shared__ __align__(16) unsigned short sm[18432];

    const int b = blockIdx.y >> 4;
    const int h = blockIdx.y & 15;
    const int q0 = blockIdx.x * 128;
    const int tid = threadIdx.x;
    const int lane = tid & 31;
    const int warp = tid >> 5;
    const float* base = qkv + (size_t)b * T_ * QKVW;
    const int hc = h * 64;

    unsigned short* Qh = sm;
    unsigned short* Ql = sm + 9216;
#pragma unroll
    for (int i = 0; i < 8; i++) {
        int f = tid + 256 * i;
        int r = f >> 4;
        int c = (f & 15) << 2;
        float4 v = *reinterpret_cast<const float4*>(
            &base[(size_t)(q0 + r) * QKVW + hc + c]);
        v.x *= 0.125f; v.y *= 0.125f; v.z *= 0.125f; v.w *= 0.125f;
        unsigned h0, h1, l0, l1;
        split4(v, h0, h1, l0, l1);
        *reinterpret_cast<uint2*>(&Qh[r * 72 + c]) = make_uint2(h0, h1);
        *reinterpret_cast<uint2*>(&Ql[r * 72 + c]) = make_uint2(l0, l1);
    }
    __syncthreads();

    unsigned qh[4][4], ql[4][4];
#pragma unroll
    for (int ks = 0; ks < 4; ks++) {
        int row = warp * 16 + (lane & 15);
        int col = ks * 16 + ((lane >> 4) << 3);
        ldmx4(qh[ks], (unsigned)__cvta_generic_to_shared(&Qh[row * 72 + col]));
        ldmx4(ql[ks], (unsigned)__cvta_generic_to_shared(&Ql[row * 72 + col]));
    }
    __syncthreads();

    unsigned short* Kh = sm;
    unsigned short* Kl = sm + 4608;
    unsigned short* Vh = sm + 9216;
    unsigned short* Vl = sm + 13824;

    float oacc[8][4];
#pragma unroll
    for (int t = 0; t < 8; t++)
#pragma unroll
        for (int j = 0; j < 4; j++) oacc[t][j] = 0.0f;
    float m0 = -1e30f, m1 = -1e30f, lsum0 = 0.0f, lsum1 = 0.0f;

    float4 Kr[4], Vr[4];
    auto load_kv = [&](int kt) {
#pragma unroll
        for (int i = 0; i < 4; i++) {
            int f = tid + 256 * i;
            int r = f >> 4, c = (f & 15) << 2;
            Kr[i] = *reinterpret_cast<const float4*>(
                &base[(size_t)(kt + r) * QKVW + E_ + hc + c]);
            Vr[i] = *reinterpret_cast<const float4*>(
                &base[(size_t)(kt + r) * QKVW + 2 * E_ + hc + c]);
        }
    };
    auto stage_kv = [&]() {
#pragma unroll
        for (int i = 0; i < 4; i++) {
            int f = tid + 256 * i;
            int r = f >> 4, c = (f & 15) << 2;
            unsigned h0, h1, l0, l1;
            split4(Kr[i], h0, h1, l0, l1);
            *reinterpret_cast<uint2*>(&Kh[r * 72 + c]) = make_uint2(h0, h1);
            *reinterpret_cast<uint2*>(&Kl[r * 72 + c]) = make_uint2(l0, l1);
            split4(Vr[i], h0, h1, l0, l1);
            *reinterpret_cast<uint2*>(&Vh[r * 72 + c]) = make_uint2(h0, h1);
            *reinterpret_cast<uint2*>(&Vl[r * 72 + c]) = make_uint2(l0, l1);
        }
    };

    load_kv(0);
    stage_kv();
    __syncthreads();

    constexpr int NIT = T_ / 64;
    for (int it = 0; it < NIT; it++) {
        if (it + 1 < NIT) load_kv((it + 1) * 64);

        float sacc[8][4];
#pragma unroll
        for (int t = 0; t < 8; t++)
#pragma unroll
            for (int j = 0; j < 4; j++) sacc[t][j] = 0.0f;

#pragma unroll
        for (int ks = 0; ks < 4; ks++) {
#pragma unroll
            for (int g = 0; g < 4; g++) {
                int row = g * 16 + ((lane >> 4) << 3) + (lane & 7);
                int col = ks * 16 + (((lane >> 3) & 1) << 3);
                unsigned bh[4], bl[4];
                ldmx4(bh, (unsigned)__cvta_generic_to_shared(&Kh[row * 72 + col]));
                ldmx4(bl, (unsigned)__cvta_generic_to_shared(&Kl[row * 72 + col]));
                mma16816(sacc[2 * g],     qh[ks], &bh[0]);
                mma16816(sacc[2 * g],     qh[ks], &bl[0]);
                mma16816(sacc[2 * g],     ql[ks], &bh[0]);
                mma16816(sacc[2 * g + 1], qh[ks], &bh[2]);
                mma16816(sacc[2 * g + 1], qh[ks], &bl[2]);
                mma16816(sacc[2 * g + 1], ql[ks], &bh[2]);
            }
        }

        float mx0 = -1e30f, mx1 = -1e30f;
#pragma unroll
        for (int t = 0; t < 8; t++) {
            mx0 = fmaxf(mx0, fmaxf(sacc[t][0], sacc[t][1]));
            mx1 = fmaxf(mx1, fmaxf(sacc[t][2], sacc[t][3]));
        }
        mx0 = fmaxf(mx0, __shfl_xor_sync(0xffffffffu, mx0, 1));
        mx0 = fmaxf(mx0, __shfl_xor_sync(0xffffffffu, mx0, 2));
        mx1 = fmaxf(mx1, __shfl_xor_sync(0xffffffffu, mx1, 1));
        mx1 = fmaxf(mx1, __shfl_xor_sync(0xffffffffu, mx1, 2));
        float mn0 = fmaxf(m0, mx0), mn1 = fmaxf(m1, mx1);
        float c0 = __expf(m0 - mn0), c1 = __expf(m1 - mn1);
        m0 = mn0; m1 = mn1;
        float s0 = 0.0f, s1 = 0.0f;
#pragma unroll
        for (int t = 0; t < 8; t++) {
            sacc[t][0] = __expf(sacc[t][0] - m0);
            sacc[t][1] = __expf(sacc[t][1] - m0);
            sacc[t][2] = __expf(sacc[t][2] - m1);
            sacc[t][3] = __expf(sacc[t][3] - m1);
            s0 += sacc[t][0] + sacc[t][1];
            s1 += sacc[t][2] + sacc[t][3];
        }
        s0 += __shfl_xor_sync(0xffffffffu, s0, 1);
        s0 += __shfl_xor_sync(0xffffffffu, s0, 2);
        s1 += __shfl_xor_sync(0xffffffffu, s1, 1);
        s1 += __shfl_xor_sync(0xffffffffu, s1, 2);
        lsum0 = lsum0 * c0 + s0;
        lsum1 = lsum1 * c1 + s1;
#pragma unroll
        for (int t = 0; t < 8; t++) {
            oacc[t][0] *= c0; oacc[t][1] *= c0;
            oacc[t][2] *= c1; oacc[t][3] *= c1;
        }

#pragma unroll
        for (int kk = 0; kk < 4; kk++) {
            unsigned ph[4], pl[4];
            ph[0] = pack2(sacc[2 * kk][0], sacc[2 * kk][1]);
            ph[1] = pack2(sacc[2 * kk][2], sacc[2 * kk][3]);
            ph[2] = pack2(sacc[2 * kk + 1][0], sacc[2 * kk + 1][1]);
            ph[3] = pack2(sacc[2 * kk + 1][2], sacc[2 * kk + 1][3]);
#pragma unroll
            for (int u2 = 0; u2 < 4; u2++) {
                const float* p = sacc[2 * kk + (u2 >> 1)];
                int o = (u2 & 1) * 2;
                float rx = __uint_as_float(ph[u2] << 16);
                float ry = __uint_as_float(ph[u2] & 0xFFFF0000u);
                pl[u2] = pack2(p[o] - rx, p[o + 1] - ry);
            }
#pragma unroll
            for (int g = 0; g < 4; g++) {
                int row = kk * 16 + (((lane >> 3) & 1) << 3) + (lane & 7);
                int col = g * 16 + ((lane >> 4) << 3);
                unsigned vh[4], vl[4];
                ldmx4t(vh, (unsigned)__cvta_generic_to_shared(&Vh[row * 72 + col]));
                ldmx4t(vl, (unsigned)__cvta_generic_to_shared(&Vl[row * 72 + col]));
                mma16816(oacc[2 * g],     ph, &vh[0]);
                mma16816(oacc[2 * g],     ph, &vl[0]);
                mma16816(oacc[2 * g],     pl, &vh[0]);
                mma16816(oacc[2 * g + 1], ph, &vh[2]);
                mma16816(oacc[2 * g + 1], ph, &vl[2]);
                mma16816(oacc[2 * g + 1], pl, &vh[2]);
            }
        }

        if (it + 1 < NIT) {
            __syncthreads();
            stage_kv();
            __syncthreads();
        }
    }

    float inv0 = 1.0f / lsum0, inv1 = 1.0f / lsum1;
    int r0 = q0 + warp * 16 + (lane >> 2);
#pragma unroll
    for (int t = 0; t < 8; t++) {
        int col = hc + t * 8 + ((lane & 3) << 1);
        *reinterpret_cast<float2*>(&out[((size_t)b * T_ + r0) * E_ + col]) =
            make_float2(oacc[t][0] * inv0, oacc[t][1] * inv0);
        *reinterpret_cast<float2*>(&out[((size_t)b * T_ + r0 + 8) * E_ + col]) =
            make_float2(oacc[t][2] * inv1, oacc[t][3] * inv1);
    }
}

// ------------------------------ orchestration -------------------------------
extern "C" void kernel_launch(void* const* d_in, const int* in_sizes, int n_in,
                              void* d_out, int out_size)
{
    const float* x_in  = (const float*)d_in[0];
    const float* Wqkv  = (const float*)d_in[1];
    const float* bqkv  = (const float*)d_in[2];
    const float* Wproj = (const float*)d_in[3];
    const float* bproj = (const float*)d_in[4];
    const float* W1    = (const float*)d_in[5];
    const float* b1    = (const float*)d_in[6];
    const float* W2    = (const float*)d_in[7];
    const float* b2    = (const float*)d_in[8];
    float* out = (float*)d_out;

    cudaFuncSetAttribute(gemm_bf<0, false, true, false>,
                         cudaFuncAttributeMaxDynamicSharedMemorySize, SMEM_G);
    cudaFuncSetAttribute(gemm_bf<0, true, true, true>,
                         cudaFuncAttributeMaxDynamicSharedMemorySize, SMEM_G);
    cudaFuncSetAttribute(gemm_bf<1, false, false, true>,
                         cudaFuncAttributeMaxDynamicSharedMemorySize, SMEM_G);

    float *gqkv, *gx, *gattn;
    __nv_bfloat16 *gxh, *gxl, *gah, *gal, *ghh, *ghl;
    __nv_bfloat16 *wqh, *wql, *wph, *wpl_, *w1h, *w1l, *w2h, *w2l;
    cudaGetSymbolAddress((void**)&gqkv, g_qkv);
    cudaGetSymbolAddress((void**)&gx, g_x);
    cudaGetSymbolAddress((void**)&gattn, g_attn);
    cudaGetSymbolAddress((void**)&gxh, g_x_hi);  cudaGetSymbolAddress((void**)&gxl, g_x_lo);
    cudaGetSymbolAddress((void**)&gah, g_a_hi);  cudaGetSymbolAddress((void**)&gal, g_a_lo);
    cudaGetSymbolAddress((void**)&ghh, g_h_hi);  cudaGetSymbolAddress((void**)&ghl, g_h_lo);
    cudaGetSymbolAddress((void**)&wqh, g_wq_hi); cudaGetSymbolAddress((void**)&wql, g_wq_lo);
    cudaGetSymbolAddress((void**)&wph, g_wp_hi); cudaGetSymbolAddress((void**)&wpl_, g_wp_lo);
    cudaGetSymbolAddress((void**)&w1h, g_w1_hi); cudaGetSymbolAddress((void**)&w1l, g_w1_lo);
    cudaGetSymbolAddress((void**)&w2h, g_w2_hi); cudaGetSymbolAddress((void**)&w2l, g_w2_lo);

    // weight transpose+split pre-pass ([K][N] fp32 -> [N][K] bf16 hi/lo)
    for (int l = 0; l < L_; l++) {
        wt_kernel<<<dim3(QKVW / 32, E_ / 64), 256>>>(
            Wqkv + (size_t)l * E_ * QKVW, wqh + (size_t)l * QKVW * E_,
            wql + (size_t)l * QKVW * E_, E_, QKVW);
        wt_kernel<<<dim3(E_ / 32, E_ / 64), 256>>>(
            Wproj + (size_t)l * E_ * E_, wph + (size_t)l * E_ * E_,
            wpl_ + (size_t)l * E_ * E_, E_, E_);
        wt_kernel<<<dim3(FFDIM / 32, E_ / 64), 256>>>(
            W1 + (size_t)l * E_ * FFDIM, w1h + (size_t)l * (size_t)FFDIM * E_,
            w1l + (size_t)l * (size_t)FFDIM * E_, E_, FFDIM);
        wt_kernel<<<dim3(E_ / 32, FFDIM / 64), 256>>>(
            W2 + (size_t)l * FFDIM * E_, w2h + (size_t)l * (size_t)E_ * FFDIM,
            w2l + (size_t)l * (size_t)E_ * FFDIM, FFDIM, E_);
    }
    // x0 planes
    split_kernel<<<(M_ * E_ / 4) / 256, 256>>>(
        (const float4*)x_in, (uint2*)gxh, (uint2*)gxl, M_ * E_ / 4);

    for (int l = 0; l < L_; l++) {
        const float* xcur = (l == 0) ? x_in : gx;

        // QKV: fp32 out for attention
        gemm_bf<0, false, true, false><<<dim3(QKVW / 128, M_ / 128), 256, SMEM_G>>>(
            gxh, gxl, wqh + (size_t)l * QKVW * E_, wql + (size_t)l * QKVW * E_,
            bqkv + (size_t)l * QKVW, nullptr, gqkv, nullptr, nullptr, M_, QKVW, E_);

        attn_mma<<<dim3(T_ / 128, B_ * H_), 256>>>(gqkv, gattn);
        split_kernel<<<(M_ * E_ / 4) / 256, 256>>>(
            (const float4*)gattn, (uint2*)gah, (uint2*)gal, M_ * E_ / 4);

        // proj + residual: fp32 x + planes
        gemm_bf<0, true, true, true><<<dim3(E_ / 128, M_ / 128), 256, SMEM_G>>>(
            gah, gal, wph + (size_t)l * E_ * E_, wpl_ + (size_t)l * E_ * E_,
            bproj + (size_t)l * E_, xcur, gx, gxh, gxl, M_, E_, E_);

        // MLP up + GELU: planes only
        gemm_bf<1, false, false, true><<<dim3(FFDIM / 128, M_ / 128), 256, SMEM_G>>>(
            gxh, gxl, w1h + (size_t)l * (size_t)FFDIM * E_,
            w1l + (size_t)l * (size_t)FFDIM * E_,
            b1 + (size_t)l * FFDIM, nullptr, nullptr, ghh, ghl, M_, FFDIM, E_);

        // MLP down + residual: fp32 (out / gx) + planes for next layer
        float* dst = (l == L_ - 1) ? out : gx;
        gemm_bf<0, true, true, true><<<dim3(E_ / 128, M_ / 128), 256, SMEM_G>>>(
            ghh, ghl, w2h + (size_t)l * (size_t)E_ * FFDIM,
            w2l + (size_t)l * (size_t)E_ * FFDIM,
            b2 + (size_t)l * E_, gx, dst, gxh, gxl, M_, E_, FFDIM);
    }
}

// round 8
// speedup vs baseline: 1.1175x; 1.1037x over previous
#include <cuda_runtime.h>
#include <cuda_bf16.h>
#include <math.h>

// Problem constants
constexpr int B_ = 2, T_ = 2048, E_ = 1024, H_ = 16, FFDIM = 4096, L_ = 4;
constexpr int M_ = B_ * T_;           // 4096 token rows
constexpr int QKVW = 3 * E_;          // 3072

// Scratch (device globals; no allocations allowed)
__device__ float g_x[M_ * E_];        // residual stream
__device__ float g_qkv[M_ * 3 * E_];  // fused qkv
__device__ float g_attn[M_ * E_];     // attention output (pre-proj)
__device__ float g_h[M_ * FFDIM];     // MLP hidden

__device__ __forceinline__ float gelu_tanh(float x) {
    float x3 = x * x * x;
    return 0.5f * x * (1.0f + tanhf(0.7978845608028654f * (x + 0.044715f * x3)));
}

// pack two fp32 into bf16x2 (first arg -> low 16 bits / element 0 in memory)
__device__ __forceinline__ unsigned pack2(float lo, float hi) {
    unsigned r;
    asm("cvt.rn.bf16x2.f32 %0, %1, %2;" : "=r"(r) : "f"(hi), "f"(lo));
    return r;
}

__device__ __forceinline__ void ldmx4(unsigned* r, unsigned addr) {
    asm volatile("ldmatrix.sync.aligned.m8n8.x4.shared.b16 {%0,%1,%2,%3}, [%4];"
        : "=r"(r[0]), "=r"(r[1]), "=r"(r[2]), "=r"(r[3]) : "r"(addr));
}
__device__ __forceinline__ void ldmx4t(unsigned* r, unsigned addr) {
    asm volatile("ldmatrix.sync.aligned.m8n8.x4.trans.shared.b16 {%0,%1,%2,%3}, [%4];"
        : "=r"(r[0]), "=r"(r[1]), "=r"(r[2]), "=r"(r[3]) : "r"(addr));
}
__device__ __forceinline__ void mma16816(float* d, const unsigned* a, const unsigned* b) {
    asm volatile("mma.sync.aligned.m16n8k16.row.col.f32.bf16.bf16.f32 "
        "{%0,%1,%2,%3}, {%4,%5,%6,%7}, {%8,%9}, {%0,%1,%2,%3};"
        : "+f"(d[0]), "+f"(d[1]), "+f"(d[2]), "+f"(d[3])
        : "r"(a[0]), "r"(a[1]), "r"(a[2]), "r"(a[3]), "r"(b[0]), "r"(b[1]));
}

// split a float4 into hi/lo bf16x2 pairs
__device__ __forceinline__ void split4(float4 v, unsigned& h0, unsigned& h1,
                                       unsigned& l0, unsigned& l1) {
    h0 = pack2(v.x, v.y); h1 = pack2(v.z, v.w);
    float rx = __uint_as_float(h0 << 16), ry = __uint_as_float(h0 & 0xFFFF0000u);
    float rz = __uint_as_float(h1 << 16), rw = __uint_as_float(h1 & 0xFFFF0000u);
    l0 = pack2(v.x - rx, v.y - ry); l1 = pack2(v.z - rz, v.w - rw);
}

// ---------------------------------------------------------------------------
// Tensor-core GEMM with bf16 3-term split (hi*hi + hi*lo + lo*hi), fp32 accum.
// 128x128 tile, BK=32, **512 threads (16 warps, 32x32 warp tiles)**.
// fp32 gmem loads, inline bf16 hi/lo conversion into smem, reg-prefetch pipe.
// 16 warps = 4/SMSP: attacks measured issue=31% warp starvation.
// ---------------------------------------------------------------------------
template <int ACT, bool RES>
__global__ void __launch_bounds__(512) gemm_mma(
    const float* __restrict__ A, const float* __restrict__ W,
    const float* __restrict__ bias, const float* __restrict__ res,
    float* __restrict__ C, int M, int N, int K)
{
    __shared__ __align__(16) unsigned short As_h[128][40];
    __shared__ __align__(16) unsigned short As_l[128][40];
    __shared__ __align__(16) unsigned short Bs_h[32][136];
    __shared__ __align__(16) unsigned short Bs_l[32][136];

    const int bm = blockIdx.y * 128;
    const int bn = blockIdx.x * 128;
    const int tid = threadIdx.x;
    const int lane = tid & 31;
    const int warp = tid >> 5;              // 0..15
    const int wm = (warp >> 2) * 32;        // 4 m-blocks of 32
    const int wn = (warp & 3) * 32;         // 4 n-blocks of 32

    float acc[2][4][4];
#pragma unroll
    for (int i = 0; i < 2; i++)
#pragma unroll
        for (int j = 0; j < 4; j++)
#pragma unroll
            for (int t = 0; t < 4; t++) acc[i][j][t] = 0.0f;

    float4 Ar[2], Br[2];

    auto load_tile = [&](int k0) {
#pragma unroll
        for (int i = 0; i < 2; i++) {
            int f = tid + 512 * i;
            int r = f >> 3, kc = (f & 7) << 2;
            Ar[i] = *reinterpret_cast<const float4*>(&A[(size_t)(bm + r) * K + k0 + kc]);
        }
#pragma unroll
        for (int i = 0; i < 2; i++) {
            int f = tid + 512 * i;
            int r = f >> 5, nc = (f & 31) << 2;
            Br[i] = *reinterpret_cast<const float4*>(&W[(size_t)(k0 + r) * N + bn + nc]);
        }
    };

    auto stage_tile = [&]() {
#pragma unroll
        for (int i = 0; i < 2; i++) {
            int f = tid + 512 * i;
            int r = f >> 3, kc = (f & 7) << 2;
            unsigned h0, h1, l0, l1;
            split4(Ar[i], h0, h1, l0, l1);
            *reinterpret_cast<uint2*>(&As_h[r][kc]) = make_uint2(h0, h1);
            *reinterpret_cast<uint2*>(&As_l[r][kc]) = make_uint2(l0, l1);
        }
#pragma unroll
        for (int i = 0; i < 2; i++) {
            int f = tid + 512 * i;
            int r = f >> 5, nc = (f & 31) << 2;
            unsigned h0, h1, l0, l1;
            split4(Br[i], h0, h1, l0, l1);
            *reinterpret_cast<uint2*>(&Bs_h[r][nc]) = make_uint2(h0, h1);
            *reinterpret_cast<uint2*>(&Bs_l[r][nc]) = make_uint2(l0, l1);
        }
    };

    const int nstages = K >> 5;
    load_tile(0);
    stage_tile();
    __syncthreads();

    for (int s = 0; s < nstages; s++) {
        if (s + 1 < nstages) load_tile((s + 1) << 5);

#pragma unroll
        for (int ks = 0; ks < 32; ks += 16) {
            unsigned bh[2][4], bl[2][4];
#pragma unroll
            for (int g = 0; g < 2; g++) {
                unsigned a0 = (unsigned)__cvta_generic_to_shared(
                    &Bs_h[ks + (lane & 15)][wn + g * 16 + ((lane >> 4) << 3)]);
                ldmx4t(bh[g], a0);
                unsigned a1 = (unsigned)__cvta_generic_to_shared(
                    &Bs_l[ks + (lane & 15)][wn + g * 16 + ((lane >> 4) << 3)]);
                ldmx4t(bl[g], a1);
            }
#pragma unroll
            for (int ma = 0; ma < 2; ma++) {
                unsigned ah[4], al[4];
                unsigned a0 = (unsigned)__cvta_generic_to_shared(
                    &As_h[wm + ma * 16 + (lane & 15)][ks + ((lane >> 4) << 3)]);
                ldmx4(ah, a0);
                unsigned a1 = (unsigned)__cvta_generic_to_shared(
                    &As_l[wm + ma * 16 + (lane & 15)][ks + ((lane >> 4) << 3)]);
                ldmx4(al, a1);
#pragma unroll
                for (int na = 0; na < 4; na++) {
                    const unsigned* bhp = &bh[na >> 1][(na & 1) * 2];
                    const unsigned* blp = &bl[na >> 1][(na & 1) * 2];
                    mma16816(acc[ma][na], ah, bhp);
                    mma16816(acc[ma][na], ah, blp);
                    mma16816(acc[ma][na], al, bhp);
                }
            }
        }

        if (s + 1 < nstages) {
            __syncthreads();
            stage_tile();
            __syncthreads();
        }
    }

    // Epilogue: bias (+GELU) (+residual); fragment layout writes
#pragma unroll
    for (int ma = 0; ma < 2; ma++) {
        int r0 = bm + wm + ma * 16 + (lane >> 2);
#pragma unroll
        for (int na = 0; na < 4; na++) {
            int c0 = bn + wn + na * 8 + ((lane & 3) << 1);
            float b0v = bias[c0], b1v = bias[c0 + 1];
            float v00 = acc[ma][na][0] + b0v, v01 = acc[ma][na][1] + b1v;
            float v10 = acc[ma][na][2] + b0v, v11 = acc[ma][na][3] + b1v;
            if (ACT == 1) {
                v00 = gelu_tanh(v00); v01 = gelu_tanh(v01);
                v10 = gelu_tanh(v10); v11 = gelu_tanh(v11);
            }
            if (RES) {
                v00 += res[(size_t)r0 * N + c0];
                v01 += res[(size_t)r0 * N + c0 + 1];
                v10 += res[(size_t)(r0 + 8) * N + c0];
                v11 += res[(size_t)(r0 + 8) * N + c0 + 1];
            }
            *reinterpret_cast<float2*>(&C[(size_t)r0 * N + c0]) = make_float2(v00, v01);
            *reinterpret_cast<float2*>(&C[(size_t)(r0 + 8) * N + c0]) = make_float2(v10, v11);
        }
    }
}

// ---------------------------------------------------------------------------
// Tensor-core flash attention (verified round-3 version, unchanged).
// ---------------------------------------------------------------------------
__global__ void __launch_bounds__(256) attn_mma(
    const float* __restrict__ qkv, float* __restrict__ out)
{
    __shared__ __align__(16) unsigned short sm[18432];

    const int b = blockIdx.y >> 4;
    const int h = blockIdx.y & 15;
    const int q0 = blockIdx.x * 128;
    const int tid = threadIdx.x;
    const int lane = tid & 31;
    const int warp = tid >> 5;
    const float* base = qkv + (size_t)b * T_ * QKVW;
    const int hc = h * 64;

    unsigned short* Qh = sm;
    unsigned short* Ql = sm + 9216;
#pragma unroll
    for (int i = 0; i < 8; i++) {
        int f = tid + 256 * i;
        int r = f >> 4;
        int c = (f & 15) << 2;
        float4 v = *reinterpret_cast<const float4*>(
            &base[(size_t)(q0 + r) * QKVW + hc + c]);
        v.x *= 0.125f; v.y *= 0.125f; v.z *= 0.125f; v.w *= 0.125f;
        unsigned h0, h1, l0, l1;
        split4(v, h0, h1, l0, l1);
        *reinterpret_cast<uint2*>(&Qh[r * 72 + c]) = make_uint2(h0, h1);
        *reinterpret_cast<uint2*>(&Ql[r * 72 + c]) = make_uint2(l0, l1);
    }
    __syncthreads();

    unsigned qh[4][4], ql[4][4];
#pragma unroll
    for (int ks = 0; ks < 4; ks++) {
        int row = warp * 16 + (lane & 15);
        int col = ks * 16 + ((lane >> 4) << 3);
        ldmx4(qh[ks], (unsigned)__cvta_generic_to_shared(&Qh[row * 72 + col]));
        ldmx4(ql[ks], (unsigned)__cvta_generic_to_shared(&Ql[row * 72 + col]));
    }
    __syncthreads();

    unsigned short* Kh = sm;
    unsigned short* Kl = sm + 4608;
    unsigned short* Vh = sm + 9216;
    unsigned short* Vl = sm + 13824;

    float oacc[8][4];
#pragma unroll
    for (int t = 0; t < 8; t++)
#pragma unroll
        for (int j = 0; j < 4; j++) oacc[t][j] = 0.0f;
    float m0 = -1e30f, m1 = -1e30f, lsum0 = 0.0f, lsum1 = 0.0f;

    float4 Kr[4], Vr[4];
    auto load_kv = [&](int kt) {
#pragma unroll
        for (int i = 0; i < 4; i++) {
            int f = tid + 256 * i;
            int r = f >> 4, c = (f & 15) << 2;
            Kr[i] = *reinterpret_cast<const float4*>(
                &base[(size_t)(kt + r) * QKVW + E_ + hc + c]);
            Vr[i] = *reinterpret_cast<const float4*>(
                &base[(size_t)(kt + r) * QKVW + 2 * E_ + hc + c]);
        }
    };
    auto stage_kv = [&]() {
#pragma unroll
        for (int i = 0; i < 4; i++) {
            int f = tid + 256 * i;
            int r = f >> 4, c = (f & 15) << 2;
            unsigned h0, h1, l0, l1;
            split4(Kr[i], h0, h1, l0, l1);
            *reinterpret_cast<uint2*>(&Kh[r * 72 + c]) = make_uint2(h0, h1);
            *reinterpret_cast<uint2*>(&Kl[r * 72 + c]) = make_uint2(l0, l1);
            split4(Vr[i], h0, h1, l0, l1);
            *reinterpret_cast<uint2*>(&Vh[r * 72 + c]) = make_uint2(h0, h1);
            *reinterpret_cast<uint2*>(&Vl[r * 72 + c]) = make_uint2(l0, l1);
        }
    };

    load_kv(0);
    stage_kv();
    __syncthreads();

    constexpr int NIT = T_ / 64;
    for (int it = 0; it < NIT; it++) {
        if (it + 1 < NIT) load_kv((it + 1) * 64);

        float sacc[8][4];
#pragma unroll
        for (int t = 0; t < 8; t++)
#pragma unroll
            for (int j = 0; j < 4; j++) sacc[t][j] = 0.0f;

#pragma unroll
        for (int ks = 0; ks < 4; ks++) {
#pragma unroll
            for (int g = 0; g < 4; g++) {
                int row = g * 16 + ((lane >> 4) << 3) + (lane & 7);
                int col = ks * 16 + (((lane >> 3) & 1) << 3);
                unsigned bh[4], bl[4];
                ldmx4(bh, (unsigned)__cvta_generic_to_shared(&Kh[row * 72 + col]));
                ldmx4(bl, (unsigned)__cvta_generic_to_shared(&Kl[row * 72 + col]));
                mma16816(sacc[2 * g],     qh[ks], &bh[0]);
                mma16816(sacc[2 * g],     qh[ks], &bl[0]);
                mma16816(sacc[2 * g],     ql[ks], &bh[0]);
                mma16816(sacc[2 * g + 1], qh[ks], &bh[2]);
                mma16816(sacc[2 * g + 1], qh[ks], &bl[2]);
                mma16816(sacc[2 * g + 1], ql[ks], &bh[2]);
            }
        }

        float mx0 = -1e30f, mx1 = -1e30f;
#pragma unroll
        for (int t = 0; t < 8; t++) {
            mx0 = fmaxf(mx0, fmaxf(sacc[t][0], sacc[t][1]));
            mx1 = fmaxf(mx1, fmaxf(sacc[t][2], sacc[t][3]));
        }
        mx0 = fmaxf(mx0, __shfl_xor_sync(0xffffffffu, mx0, 1));
        mx0 = fmaxf(mx0, __shfl_xor_sync(0xffffffffu, mx0, 2));
        mx1 = fmaxf(mx1, __shfl_xor_sync(0xffffffffu, mx1, 1));
        mx1 = fmaxf(mx1, __shfl_xor_sync(0xffffffffu, mx1, 2));
        float mn0 = fmaxf(m0, mx0), mn1 = fmaxf(m1, mx1);
        float c0 = __expf(m0 - mn0), c1 = __expf(m1 - mn1);
        m0 = mn0; m1 = mn1;
        float s0 = 0.0f, s1 = 0.0f;
#pragma unroll
        for (int t = 0; t < 8; t++) {
            sacc[t][0] = __expf(sacc[t][0] - m0);
            sacc[t][1] = __expf(sacc[t][1] - m0);
            sacc[t][2] = __expf(sacc[t][2] - m1);
            sacc[t][3] = __expf(sacc[t][3] - m1);
            s0 += sacc[t][0] + sacc[t][1];
            s1 += sacc[t][2] + sacc[t][3];
        }
        s0 += __shfl_xor_sync(0xffffffffu, s0, 1);
        s0 += __shfl_xor_sync(0xffffffffu, s0, 2);
        s1 += __shfl_xor_sync(0xffffffffu, s1, 1);
        s1 += __shfl_xor_sync(0xffffffffu, s1, 2);
        lsum0 = lsum0 * c0 + s0;
        lsum1 = lsum1 * c1 + s1;
#pragma unroll
        for (int t = 0; t < 8; t++) {
            oacc[t][0] *= c0; oacc[t][1] *= c0;
            oacc[t][2] *= c1; oacc[t][3] *= c1;
        }

#pragma unroll
        for (int kk = 0; kk < 4; kk++) {
            unsigned ph[4], pl[4];
            ph[0] = pack2(sacc[2 * kk][0], sacc[2 * kk][1]);
            ph[1] = pack2(sacc[2 * kk][2], sacc[2 * kk][3]);
            ph[2] = pack2(sacc[2 * kk + 1][0], sacc[2 * kk + 1][1]);
            ph[3] = pack2(sacc[2 * kk + 1][2], sacc[2 * kk + 1][3]);
#pragma unroll
            for (int u2 = 0; u2 < 4; u2++) {
                const float* p = sacc[2 * kk + (u2 >> 1)];
                int o = (u2 & 1) * 2;
                float rx = __uint_as_float(ph[u2] << 16);
                float ry = __uint_as_float(ph[u2] & 0xFFFF0000u);
                pl[u2] = pack2(p[o] - rx, p[o + 1] - ry);
            }
#pragma unroll
            for (int g = 0; g < 4; g++) {
                int row = kk * 16 + (((lane >> 3) & 1) << 3) + (lane & 7);
                int col = g * 16 + ((lane >> 4) << 3);
                unsigned vh[4], vl[4];
                ldmx4t(vh, (unsigned)__cvta_generic_to_shared(&Vh[row * 72 + col]));
                ldmx4t(vl, (unsigned)__cvta_generic_to_shared(&Vl[row * 72 + col]));
                mma16816(oacc[2 * g],     ph, &vh[0]);
                mma16816(oacc[2 * g],     ph, &vl[0]);
                mma16816(oacc[2 * g],     pl, &vh[0]);
                mma16816(oacc[2 * g + 1], ph, &vh[2]);
                mma16816(oacc[2 * g + 1], ph, &vl[2]);
                mma16816(oacc[2 * g + 1], pl, &vh[2]);
            }
        }

        if (it + 1 < NIT) {
            __syncthreads();
            stage_kv();
            __syncthreads();
        }
    }

    float inv0 = 1.0f / lsum0, inv1 = 1.0f / lsum1;
    int r0 = q0 + warp * 16 + (lane >> 2);
#pragma unroll
    for (int t = 0; t < 8; t++) {
        int col = hc + t * 8 + ((lane & 3) << 1);
        *reinterpret_cast<float2*>(&out[((size_t)b * T_ + r0) * E_ + col]) =
            make_float2(oacc[t][0] * inv0, oacc[t][1] * inv0);
        *reinterpret_cast<float2*>(&out[((size_t)b * T_ + r0 + 8) * E_ + col]) =
            make_float2(oacc[t][2] * inv1, oacc[t][3] * inv1);
    }
}

// ---------------------------------------------------------------------------
// Orchestration (round-3 structure: no pre-pass, no planes)
// ---------------------------------------------------------------------------
extern "C" void kernel_launch(void* const* d_in, const int* in_sizes, int n_in,
                              void* d_out, int out_size)
{
    const float* x_in  = (const float*)d_in[0];
    const float* Wqkv  = (const float*)d_in[1];
    const float* bqkv  = (const float*)d_in[2];
    const float* Wproj = (const float*)d_in[3];
    const float* bproj = (const float*)d_in[4];
    const float* W1    = (const float*)d_in[5];
    const float* b1    = (const float*)d_in[6];
    const float* W2    = (const float*)d_in[7];
    const float* b2    = (const float*)d_in[8];
    float* out = (float*)d_out;

    float *gx, *gqkv, *gattn, *gh;
    cudaGetSymbolAddress((void**)&gx, g_x);
    cudaGetSymbolAddress((void**)&gqkv, g_qkv);
    cudaGetSymbolAddress((void**)&gattn, g_attn);
    cudaGetSymbolAddress((void**)&gh, g_h);

    dim3 blk(512);
    for (int l = 0; l < L_; l++) {
        const float* xcur = (l == 0) ? x_in : gx;

        gemm_mma<0, false><<<dim3(QKVW / 128, M_ / 128), blk>>>(
            xcur, Wqkv + (size_t)l * E_ * QKVW, bqkv + (size_t)l * QKVW,
            nullptr, gqkv, M_, QKVW, E_);

        attn_mma<<<dim3(T_ / 128, B_ * H_), 256>>>(gqkv, gattn);

        gemm_mma<0, true><<<dim3(E_ / 128, M_ / 128), blk>>>(
            gattn, Wproj + (size_t)l * E_ * E_, bproj + (size_t)l * E_,
            xcur, gx, M_, E_, E_);

        gemm_mma<1, false><<<dim3(FFDIM / 128, M_ / 128), blk>>>(
            gx, W1 + (size_t)l * E_ * FFDIM, b1 + (size_t)l * FFDIM,
            nullptr, gh, M_, FFDIM, E_);

        float* dst = (l == L_ - 1) ? out : gx;
        gemm_mma<0, true><<<dim3(E_ / 128, M_ / 128), blk>>>(
            gh, W2 + (size_t)l * FFDIM * E_, b2 + (size_t)l * E_,
            gx, dst, M_, E_, FFDIM);
    }
}